// round 9
// baseline (speedup 1.0000x reference)
#include <cuda_runtime.h>
#include <math.h>

#define BB 16
#define H 512
#define W 512
#define NH 64
#define NW 64
#define HW (H*W)
#define NCTA1 128   // k1 CTAs per batch (8 x 16)

#define PROWB 560u                 // pair-row byte stride: 70 float2; 140 banks ≡ 12 mod 32 -> conflict-free
#define NPROW 22u                  // pair rows 0..21: (in[p], in[p+16]) covers 38-row halo
#define PBUF  (NPROW*PROWB)        // 12320 B
#define NSTAGE 1540                // NPROW*70 float2 elements per channel
#define NSLOT 13                   // ceil(1540/128)

// Scratch (no allocations allowed)
__device__ unsigned char g_lbp8[BB*HW];   // LBP code 0..9 as u8
__device__ float g_partials[BB*NCTA1*3]; // per-CTA rgb sums
__device__ int   g_maxbits[BB];          // per-batch max(code) as float bits
__device__ float g_scale[BB*3];
__device__ float g_invmx[BB];

// D[4,:] and D[3,:] of the 8x8 DCT-II matrix (with row scaling)
__constant__ float c_D4[8] = {
    0.35355339059327373f, -0.35355339059327373f, -0.35355339059327373f,  0.35355339059327373f,
    0.35355339059327373f, -0.35355339059327373f, -0.35355339059327373f,  0.35355339059327373f };
__constant__ float c_D3[8] = {
    0.4157348061512726f,  -0.0975451610080642f,  -0.4903926402016152f,  -0.2777851165098011f,
    0.2777851165098011f,   0.4903926402016152f,   0.0975451610080642f,  -0.4157348061512726f };

__device__ __forceinline__ unsigned long long pack2(float lo, float hi) {
    unsigned long long r;
    asm("mov.b64 %0, {%1, %2};" : "=l"(r) : "f"(lo), "f"(hi));
    return r;
}
__device__ __forceinline__ float2 unpack2(unsigned long long v) {
    float2 f;
    asm("mov.b64 {%0, %1}, %2;" : "=f"(f.x), "=f"(f.y) : "l"(v));
    return f;
}
__device__ __forceinline__ void ffma2(unsigned long long& d, unsigned long long a, unsigned long long b) {
    asm("fma.rn.f32x2 %0, %1, %2, %0;" : "+l"(d) : "l"(a), "l"(b));
}

__global__ void k0_zero() {
    if (threadIdx.x < BB) g_maxbits[threadIdx.x] = 0;
}

// ---------------- K1: LBP code (u8) + per-batch max + rgb partial sums --------
// 64x32 output tile. Halo buffer 34 rows x 72 cols; logical halo col gx = bx*64-4 + col.
// LBP center x -> col x+4.
__global__ __launch_bounds__(256) void k1_lbp(const float* __restrict__ frame) {
    const int b  = blockIdx.z;
    const int bx = blockIdx.x;   // 0..7
    const int by = blockIdx.y;   // 0..15
    const int tid = threadIdx.x;

    __shared__ float gs[34][72];
    __shared__ float4 wred[8];

    const float* fb = frame + b*3*HW;

    float sr = 0.f, sg = 0.f, sb = 0.f;

    if (bx >= 1 && bx <= 6) {
        // vectorized: 34 rows x 18 float4 (72 floats), aligned base
        const int gxb = bx*64 - 4;
        for (int i = tid; i < 34*18; i += 256) {
            int ly = i / 18, q = i - ly*18;
            int gy = by*32 + ly - 1; gy = min(max(gy, 0), H-1);
            const float* pr = fb + 0*HW + gy*W + gxb + q*4;
            const float* pg = fb + 1*HW + gy*W + gxb + q*4;
            const float* pb = fb + 2*HW + gy*W + gxb + q*4;
            float4 r4 = *(const float4*)pr;
            float4 g4 = *(const float4*)pg;
            float4 b4 = *(const float4*)pb;
            gs[ly][q*4+0] = 0.299f*r4.x + 0.587f*g4.x + 0.114f*b4.x;
            gs[ly][q*4+1] = 0.299f*r4.y + 0.587f*g4.y + 0.114f*b4.y;
            gs[ly][q*4+2] = 0.299f*r4.z + 0.587f*g4.z + 0.114f*b4.z;
            gs[ly][q*4+3] = 0.299f*r4.w + 0.587f*g4.w + 0.114f*b4.w;
            if (ly >= 1 && ly <= 32 && q >= 1 && q <= 16) {
                sr += r4.x + r4.y + r4.z + r4.w;
                sg += g4.x + g4.y + g4.z + g4.w;
                sb += b4.x + b4.y + b4.z + b4.w;
            }
        }
    } else {
        // scalar edge path: lx 0..65 represents gx = bx*64 - 1 + lx, col = lx+3
        for (int i = tid; i < 34*66; i += 256) {
            int ly = i / 66, lx = i % 66;
            int gy = by*32 + ly - 1; gy = min(max(gy, 0), H-1);
            int gx = bx*64 + lx - 1; gx = min(max(gx, 0), W-1);
            int off = gy*W + gx;
            float r  = fb[0*HW + off];
            float g  = fb[1*HW + off];
            float bl = fb[2*HW + off];
            gs[ly][lx+3] = 0.299f*r + 0.587f*g + 0.114f*bl;
            if (ly >= 1 && ly <= 32 && lx >= 1 && lx <= 64) { sr += r; sg += g; sb += bl; }
        }
    }
    __syncthreads();

    float lmax = 0.f;
    unsigned char* lbp = g_lbp8 + b*HW;
    #pragma unroll
    for (int k = 0; k < 8; k++) {
        int idx = tid + k*256;
        int y = idx >> 6, x = idx & 63;
        int ly = y + 1, lx = x + 4;
        float c = gs[ly][lx];
        int b0 = gs[ly-1][lx  ] >= c;
        int b1 = gs[ly-1][lx+1] >= c;
        int b2 = gs[ly  ][lx+1] >= c;
        int b3 = gs[ly+1][lx+1] >= c;
        int b4 = gs[ly+1][lx  ] >= c;
        int b5 = gs[ly+1][lx-1] >= c;
        int b6 = gs[ly  ][lx-1] >= c;
        int b7 = gs[ly-1][lx-1] >= c;
        int s = b0+b1+b2+b3+b4+b5+b6+b7;
        int trans = abs(b0-b7)+abs(b1-b0)+abs(b2-b1)+abs(b3-b2)
                  + abs(b4-b3)+abs(b5-b4)+abs(b6-b5)+abs(b7-b6);
        int code = (trans <= 2) ? s : 9;
        lbp[(by*32 + y)*W + bx*64 + x] = (unsigned char)code;
        lmax = fmaxf(lmax, (float)code);
    }

    #pragma unroll
    for (int off = 16; off > 0; off >>= 1) {
        sr   += __shfl_down_sync(0xffffffffu, sr, off);
        sg   += __shfl_down_sync(0xffffffffu, sg, off);
        sb   += __shfl_down_sync(0xffffffffu, sb, off);
        lmax  = fmaxf(lmax, __shfl_down_sync(0xffffffffu, lmax, off));
    }
    if ((tid & 31) == 0) wred[tid >> 5] = make_float4(sr, sg, sb, lmax);
    __syncthreads();
    if (tid == 0) {
        float4 a = wred[0];
        #pragma unroll
        for (int w = 1; w < 8; w++) {
            float4 c = wred[w];
            a.x += c.x; a.y += c.y; a.z += c.z; a.w = fmaxf(a.w, c.w);
        }
        int pb = (b*NCTA1 + by*8 + bx)*3;
        g_partials[pb+0] = a.x;
        g_partials[pb+1] = a.y;
        g_partials[pb+2] = a.z;
        atomicMax(&g_maxbits[b], __float_as_int(a.w));
    }
}

// ---------------- K2: channel-attention scale + 1/max ------------------------
__global__ void k2_scale(const float* __restrict__ caw1, const float* __restrict__ caw2) {
    int b = threadIdx.x;
    if (b >= BB) return;
    float sr = 0.f, sg = 0.f, sb = 0.f;
    for (int i = 0; i < NCTA1; i++) {
        sr += g_partials[(b*NCTA1+i)*3+0];
        sg += g_partials[(b*NCTA1+i)*3+1];
        sb += g_partials[(b*NCTA1+i)*3+2];
    }
    const float inv = 1.0f / (float)(HW);
    float mr = sr*inv, mg = sg*inv, mb = sb*inv;
    float p[3];
    p[0] =  0.299f*mr + 0.587f*mg + 0.114f*mb;
    p[1] = -0.147f*mr - 0.289f*mg + 0.436f*mb;
    p[2] =  0.615f*mr - 0.515f*mg - 0.100f*mb;
    float h[3];
    #pragma unroll
    for (int i = 0; i < 3; i++) {
        float a = p[0]*caw1[i*3+0] + p[1]*caw1[i*3+1] + p[2]*caw1[i*3+2];
        h[i] = fmaxf(a, 0.f);
    }
    #pragma unroll
    for (int i = 0; i < 3; i++) {
        float a = h[0]*caw2[i*3+0] + h[1]*caw2[i*3+1] + h[2]*caw2[i*3+2];
        g_scale[b*3+i] = 1.0f / (1.0f + expf(-a));
    }
    g_invmx[b] = 1.0f / __int_as_float(g_maxbits[b]);
}

// Prefetch channel c into registers (all LDGs issue up-front, high MLP).
__device__ __forceinline__ void prefetch_ch(float2* pf, int c,
                                            const float* __restrict__ fb,
                                            const unsigned char* __restrict__ lb,
                                            float invmx, int y0, int x0, int tid) {
    if (c < 3) {
        const float* src = fb + c*HW;
        #pragma unroll
        for (int k = 0; k < NSLOT; k++) {
            int i = tid + k*128;
            if (i < NSTAGE) {
                int p = i / 70, lx = i - p*70;
                int gy = y0 + p, gx = x0 + lx;
                bool inx = (gx >= 0 && gx < W);
                float lo = (inx && gy    >= 0 && gy    < H) ? src[gy*W + gx]      : 0.f;
                float hi = (inx && gy+16 >= 0 && gy+16 < H) ? src[(gy+16)*W + gx] : 0.f;
                pf[k] = make_float2(lo, hi);
            }
        }
    } else {
        #pragma unroll
        for (int k = 0; k < NSLOT; k++) {
            int i = tid + k*128;
            if (i < NSTAGE) {
                int p = i / 70, lx = i - p*70;
                int gy = y0 + p, gx = x0 + lx;
                bool inx = (gx >= 0 && gx < W);
                float lo = (inx && gy    >= 0 && gy    < H) ? (float)lb[gy*W + gx]*invmx      : 0.f;
                float hi = (inx && gy+16 >= 0 && gy+16 < H) ? (float)lb[(gy+16)*W + gx]*invmx : 0.f;
                pf[k] = make_float2(lo, hi);
            }
        }
    }
}

__device__ __forceinline__ void store_ch(unsigned char* dst, const float2* pf, int tid) {
    #pragma unroll
    for (int k = 0; k < NSLOT; k++) {
        int i = tid + k*128;
        if (i < NSTAGE) {
            int p = i / 70, lx = i - p*70;
            *(float2*)(dst + (unsigned)p*PROWB + (unsigned)lx*8u) = pf[k];
        }
    }
}

// ---------------- K3 fused: conv (f32x2, rows ty & ty+16) -> mask+strength -> embed
// Output tile per CTA: 64 (x) x 32 (y). 128 threads: ty=tid&15, tx=tid>>4.
__global__ __launch_bounds__(128, 5) void k3_fused(const float* __restrict__ frame,
                                                   const float* __restrict__ sa_w,
                                                   const float* __restrict__ sa_b,
                                                   const int* __restrict__ wm, int L,
                                                   float* __restrict__ out_rgb,
                                                   float* __restrict__ out_mask) {
    const int b  = blockIdx.z;
    const int bx = blockIdx.x;   // 0..7
    const int by = blockIdx.y;   // 0..15
    const int tid = threadIdx.x;
    const int ty = tid & 15;     // 0..15
    const int tx = tid >> 4;     // 0..7

    __shared__ __align__(16) unsigned char praw[2][PBUF];
    __shared__ unsigned long long wdup[4][49];
    __shared__ float s_bias;
    __shared__ float s_part[32][8];
    __shared__ float s_str[4][8];

    for (int i = tid; i < 196; i += 128) {
        float w = sa_w[i];
        wdup[i/49][i%49] = pack2(w, w);
    }
    if (tid == 0) s_bias = sa_b[0];

    const float invmx = g_invmx[b];
    const float* fb = frame + b*3*HW;
    const unsigned char* lb = g_lbp8 + b*HW;
    const int y0 = by*32 - 3, x0 = bx*64 - 3;

    float2 pf[NSLOT];

    // channel 0: prefetch + store (startup, latency exposed once)
    prefetch_ch(pf, 0, fb, lb, invmx, y0, x0, tid);
    store_ch(praw[0], pf, tid);
    __syncthreads();

    unsigned long long Q[8];
    {
        const unsigned long long qb = pack2(s_bias, s_bias);
        #pragma unroll
        for (int o = 0; o < 8; o++) Q[o] = qb;
    }

    #pragma unroll 1
    for (int c = 0; c < 4; c++) {
        const int bi = c & 1;
        // issue LDGs for channel c+1 (consumed after compute -> latency hidden)
        if (c < 3) prefetch_ch(pf, c+1, fb, lb, invmx, y0, x0, tid);

        const unsigned char* buf = praw[bi] + (unsigned)ty*PROWB + (unsigned)tx*64u;
        #pragma unroll
        for (int ky = 0; ky < 7; ky++) {
            const unsigned char* rp = buf + (unsigned)ky*PROWB;
            unsigned long long vrow[14];
            #pragma unroll
            for (int u = 0; u < 7; u++) {
                ulonglong2 v = *(const ulonglong2*)(rp + 16u*u);
                vrow[2*u]   = v.x;
                vrow[2*u+1] = v.y;
            }
            #pragma unroll
            for (int kx = 0; kx < 7; kx++) {
                unsigned long long w = wdup[c][ky*7 + kx];
                #pragma unroll
                for (int o = 0; o < 8; o++) ffma2(Q[o], vrow[o + kx], w);
            }
        }

        if (c < 3) store_ch(praw[bi^1], pf, tid);
        __syncthreads();
    }

    // ---- mask + per-row block partials ----
    float m0[8], m1[8];
    float ms0 = 0.f, ms1 = 0.f;
    #pragma unroll
    for (int o = 0; o < 8; o++) {
        float2 q = unpack2(Q[o]);
        m0[o] = 1.0f / (1.0f + expf(-q.x));
        m1[o] = 1.0f / (1.0f + expf(-q.y));
        ms0 += m0[o];
        ms1 += m1[o];
    }
    s_part[ty][tx]      = ms0;
    s_part[ty + 16][tx] = ms1;
    __syncthreads();

    if (tid < 32) {
        int bh = tid >> 3, bw = tid & 7;
        float s = 0.f;
        #pragma unroll
        for (int i = 0; i < 8; i++) s += s_part[bh*8 + i][bw];
        s_str[bh][bw] = s * (1.0f/64.0f);
    }
    __syncthreads();

    // ---- write mask, embed watermark, write rgb (rows gy0 and gy0+16) ----
    const int gy0 = by*32 + ty;
    const int gx0 = bx*64 + tx*8;

    if (out_mask) {
        float* mp = out_mask + b*HW + gy0*W + gx0;
        *(float4*)(mp)            = make_float4(m0[0], m0[1], m0[2], m0[3]);
        *(float4*)(mp + 4)        = make_float4(m0[4], m0[5], m0[6], m0[7]);
        *(float4*)(mp + 16*W)     = make_float4(m1[0], m1[1], m1[2], m1[3]);
        *(float4*)(mp + 16*W + 4) = make_float4(m1[4], m1[5], m1[6], m1[7]);
    }

    const float sc0 = g_scale[b*3+0];
    const float sc1 = g_scale[b*3+1];
    const float sc2 = g_scale[b*3+2];
    const int bw_g = gx0 >> 3;
    const float d4 = c_D4[gy0 & 7];

    const float* fin = fb + gy0*W + gx0;
    float* outb = out_rgb + b*3*HW + gy0*W + gx0;
    #pragma unroll
    for (int rr = 0; rr < 2; rr++) {
        const int gy = gy0 + rr*16;
        const int bh_g = gy >> 3;
        const float strength = s_str[(ty >> 3) + rr*2][tx];
        const int bit = wm[(bh_g*NW + bw_g) % L];
        const float delta = 0.05f * strength * (2.0f*(float)bit - 1.0f) * d4;

        const float* frow = fin + rr*16*W;
        float4 R0 = *(const float4*)(frow + 0*HW);
        float4 R1 = *(const float4*)(frow + 0*HW + 4);
        float4 G0 = *(const float4*)(frow + 1*HW);
        float4 G1 = *(const float4*)(frow + 1*HW + 4);
        float4 B0 = *(const float4*)(frow + 2*HW);
        float4 B1 = *(const float4*)(frow + 2*HW + 4);
        float rv[8] = { R0.x, R0.y, R0.z, R0.w, R1.x, R1.y, R1.z, R1.w };
        float gv[8] = { G0.x, G0.y, G0.z, G0.w, G1.x, G1.y, G1.z, G1.w };
        float bv[8] = { B0.x, B0.y, B0.z, B0.w, B1.x, B1.y, B1.z, B1.w };
        float ro[8], go[8], bo[8];
        #pragma unroll
        for (int o = 0; o < 8; o++) {
            float r  = rv[o], g = gv[o], bl = bv[o];
            float Y =  0.299f*r + 0.587f*g + 0.114f*bl;
            float U = -0.147f*r - 0.289f*g + 0.436f*bl;
            float V =  0.615f*r - 0.515f*g - 0.100f*bl;
            float wy = Y * sc0;
            float wu = U * sc1;
            float wv = V * sc2;
            float ym = wy + delta * c_D3[o];
            ro[o] = ym + 1.140f*wv;
            go[o] = ym - 0.395f*wu - 0.581f*wv;
            bo[o] = ym + 2.032f*wu;
        }
        float* orow = outb + rr*16*W;
        *(float4*)(orow + 0*HW)     = make_float4(ro[0], ro[1], ro[2], ro[3]);
        *(float4*)(orow + 0*HW + 4) = make_float4(ro[4], ro[5], ro[6], ro[7]);
        *(float4*)(orow + 1*HW)     = make_float4(go[0], go[1], go[2], go[3]);
        *(float4*)(orow + 1*HW + 4) = make_float4(go[4], go[5], go[6], go[7]);
        *(float4*)(orow + 2*HW)     = make_float4(bo[0], bo[1], bo[2], bo[3]);
        *(float4*)(orow + 2*HW + 4) = make_float4(bo[4], bo[5], bo[6], bo[7]);
    }
}

extern "C" void kernel_launch(void* const* d_in, const int* in_sizes, int n_in,
                              void* d_out, int out_size) {
    const float* frame = (const float*)d_in[0];
    const int*   wm    = (const int*)  d_in[1];
    const float* sa_w  = (const float*)d_in[2];
    const float* sa_b  = (const float*)d_in[3];
    const float* ca_w1 = (const float*)d_in[4];
    const float* ca_w2 = (const float*)d_in[5];
    int L = in_sizes[1];

    float* out = (float*)d_out;
    const long rgbN = (long)BB*3*HW;
    float* out_mask = ((long)out_size >= rgbN + (long)BB*HW) ? out + rgbN : nullptr;

    k0_zero<<<1, 32>>>();

    dim3 grd1(8, 16, BB);
    k1_lbp<<<grd1, 256>>>(frame);

    k2_scale<<<1, 16>>>(ca_w1, ca_w2);

    dim3 grd3(8, 16, BB);
    k3_fused<<<grd3, 128>>>(frame, sa_w, sa_b, wm, L, out, out_mask);
}

// round 12
// speedup vs baseline: 1.0946x; 1.0946x over previous
#include <cuda_runtime.h>
#include <math.h>

#define BB 16
#define H 512
#define W 512
#define NH 64
#define NW 64
#define HW (H*W)
#define NCTA1 128   // k1 CTAs per batch (8 x 16)

// Conv tile row base (in floats): 400B linear stride + rotating 16B offset.
// Proofs: containment (gap>=2 floats at wrap), 16B alignment, and 8 distinct
// 16B slots mod 128B per 8-lane phase (rows step 2) -> conflict-free LDS.128.
#define ROWOFF_F(r) ((r)*100 + (((r)>>1)&7)*4)
#define BUF_FLOATS 3840   // 38 rows * 100 + slack = 15360B

// Scratch (no allocations allowed)
__device__ unsigned char g_lbp8[BB*HW];     // LBP code 0..9 as u8
__device__ float4 g_partials4[BB*NCTA1];    // per-CTA {sum_r, sum_g, sum_b, max_code}
__device__ float g_scale[BB*3];
__device__ float g_invmx[BB];

// D[4,:] and D[3,:] of the 8x8 DCT-II matrix (with row scaling)
__constant__ float c_D4[8] = {
    0.35355339059327373f, -0.35355339059327373f, -0.35355339059327373f,  0.35355339059327373f,
    0.35355339059327373f, -0.35355339059327373f, -0.35355339059327373f,  0.35355339059327373f };
__constant__ float c_D3[8] = {
    0.4157348061512726f,  -0.0975451610080642f,  -0.4903926402016152f,  -0.2777851165098011f,
    0.2777851165098011f,   0.4903926402016152f,   0.0975451610080642f,  -0.4157348061512726f };

__device__ __forceinline__ unsigned long long pack2(float lo, float hi) {
    unsigned long long r;
    asm("mov.b64 %0, {%1, %2};" : "=l"(r) : "f"(lo), "f"(hi));
    return r;
}
__device__ __forceinline__ float2 unpack2(unsigned long long v) {
    float2 f;
    asm("mov.b64 {%0, %1}, %2;" : "=f"(f.x), "=f"(f.y) : "l"(v));
    return f;
}
__device__ __forceinline__ void ffma2(unsigned long long& d, unsigned long long a, unsigned long long b) {
    asm("fma.rn.f32x2 %0, %1, %2, %0;" : "+l"(d) : "l"(a), "l"(b));
}

// ---------------- K1: LBP code (u8) + per-batch max + rgb partial sums --------
__global__ __launch_bounds__(256) void k1_lbp(const float* __restrict__ frame) {
    const int b  = blockIdx.z;
    const int bx = blockIdx.x;   // 0..7
    const int by = blockIdx.y;   // 0..15
    const int tid = threadIdx.x;

    __shared__ float gs[34][68];
    __shared__ float4 wred[8];

    const float* fb = frame + b*3*HW;

    float sr = 0.f, sg = 0.f, sb = 0.f;
    for (int i = tid; i < 34*66; i += 256) {
        int ly = i / 66, lx = i % 66;
        int gy = by*32 + ly - 1; gy = min(max(gy, 0), H-1);
        int gx = bx*64 + lx - 1; gx = min(max(gx, 0), W-1);
        int off = gy*W + gx;
        float r  = fb[0*HW + off];
        float g  = fb[1*HW + off];
        float bl = fb[2*HW + off];
        gs[ly][lx] = 0.299f*r + 0.587f*g + 0.114f*bl;
        if (ly >= 1 && ly <= 32 && lx >= 1 && lx <= 64) { sr += r; sg += g; sb += bl; }
    }
    __syncthreads();

    float lmax = 0.f;
    unsigned char* lbp = g_lbp8 + b*HW;
    #pragma unroll
    for (int k = 0; k < 8; k++) {
        int idx = tid + k*256;
        int y = idx >> 6, x = idx & 63;
        int ly = y + 1, lx = x + 1;
        float c = gs[ly][lx];
        int b0 = gs[ly-1][lx  ] >= c;
        int b1 = gs[ly-1][lx+1] >= c;
        int b2 = gs[ly  ][lx+1] >= c;
        int b3 = gs[ly+1][lx+1] >= c;
        int b4 = gs[ly+1][lx  ] >= c;
        int b5 = gs[ly+1][lx-1] >= c;
        int b6 = gs[ly  ][lx-1] >= c;
        int b7 = gs[ly-1][lx-1] >= c;
        int s = b0+b1+b2+b3+b4+b5+b6+b7;
        int trans = abs(b0-b7)+abs(b1-b0)+abs(b2-b1)+abs(b3-b2)
                  + abs(b4-b3)+abs(b5-b4)+abs(b6-b5)+abs(b7-b6);
        int code = (trans <= 2) ? s : 9;
        lbp[(by*32 + y)*W + bx*64 + x] = (unsigned char)code;
        lmax = fmaxf(lmax, (float)code);
    }

    #pragma unroll
    for (int off = 16; off > 0; off >>= 1) {
        sr   += __shfl_down_sync(0xffffffffu, sr, off);
        sg   += __shfl_down_sync(0xffffffffu, sg, off);
        sb   += __shfl_down_sync(0xffffffffu, sb, off);
        lmax  = fmaxf(lmax, __shfl_down_sync(0xffffffffu, lmax, off));
    }
    if ((tid & 31) == 0) wred[tid >> 5] = make_float4(sr, sg, sb, lmax);
    __syncthreads();
    if (tid == 0) {
        float4 a = wred[0];
        #pragma unroll
        for (int w = 1; w < 8; w++) {
            float4 c = wred[w];
            a.x += c.x; a.y += c.y; a.z += c.z; a.w = fmaxf(a.w, c.w);
        }
        g_partials4[b*NCTA1 + by*8 + bx] = a;
    }
}

// ---------------- K2: channel-attention scale + 1/max ------------------------
__global__ void k2_scale(const float* __restrict__ caw1, const float* __restrict__ caw2) {
    int b = threadIdx.x;
    if (b >= BB) return;
    float sr = 0.f, sg = 0.f, sb = 0.f, mx = 0.f;
    for (int i = 0; i < NCTA1; i++) {
        float4 a = g_partials4[b*NCTA1 + i];
        sr += a.x; sg += a.y; sb += a.z; mx = fmaxf(mx, a.w);
    }
    const float inv = 1.0f / (float)(HW);
    float mr = sr*inv, mg = sg*inv, mb = sb*inv;
    float p[3];
    p[0] =  0.299f*mr + 0.587f*mg + 0.114f*mb;
    p[1] = -0.147f*mr - 0.289f*mg + 0.436f*mb;
    p[2] =  0.615f*mr - 0.515f*mg - 0.100f*mb;
    float h[3];
    #pragma unroll
    for (int i = 0; i < 3; i++) {
        float a = p[0]*caw1[i*3+0] + p[1]*caw1[i*3+1] + p[2]*caw1[i*3+2];
        h[i] = fmaxf(a, 0.f);
    }
    #pragma unroll
    for (int i = 0; i < 3; i++) {
        float a = h[0]*caw2[i*3+0] + h[1]*caw2[i*3+1] + h[2]*caw2[i*3+2];
        g_scale[b*3+i] = 1.0f / (1.0f + expf(-a));
    }
    g_invmx[b] = 1.0f / mx;
}

// ---------------- K3 fused: staged conv (f32x2 dup) -> mask+strength -> embed
// Output tile per CTA: 64 (x) x 32 (y). 128 threads: ty=tid&15 (row pair),
// tx=tid>>4 (8-wide x strip). Thread computes rows 2ty,2ty+1 x 8 x-outputs.
__global__ __launch_bounds__(128, 7) void k3_fused(const float* __restrict__ frame,
                                                   const float* __restrict__ sa_w,
                                                   const float* __restrict__ sa_b,
                                                   const int* __restrict__ wm, int L,
                                                   float* __restrict__ out_rgb,
                                                   float* __restrict__ out_mask) {
    const int b  = blockIdx.z;
    const int bx = blockIdx.x;   // 0..7
    const int by = blockIdx.y;   // 0..15
    const int tid = threadIdx.x;
    const int ty = tid & 15;     // 0..15  (phase-varying -> conflict-free LDS)
    const int tx = tid >> 4;     // 0..7

    __shared__ __align__(16) float buf[BUF_FLOATS]; // one channel stage, offset layout
    __shared__ __align__(8)  float2 wp[4][8][7];    // (w[rr], w[rr-1]) pairs, zero-padded
    __shared__ float s_bias;
    __shared__ float s_part[16][8];
    __shared__ float s_str[4][8];

    // Pre-pack weight pairs: lo half drives acc0 (row 2ty), hi half acc1 (2ty+1)
    for (int i = tid; i < 224; i += 128) {
        int c = i / 56, rem = i % 56, rr = rem / 7, kx = rem % 7;
        float lo = (rr < 7) ? sa_w[c*49 + rr*7 + kx]     : 0.f;
        float hi = (rr >= 1) ? sa_w[c*49 + (rr-1)*7 + kx] : 0.f;
        wp[c][rr][kx] = make_float2(lo, hi);
    }
    if (tid == 0) s_bias = sa_b[0];

    const float invmx = g_invmx[b];
    const float* fb = frame + b*3*HW;
    const unsigned char* lb = g_lbp8 + b*HW;
    const int y0 = by*32 - 3, x0 = bx*64 - 3;

    __syncthreads();

    unsigned long long Q[8];
    {
        const unsigned long long qb = pack2(s_bias, s_bias);
        #pragma unroll
        for (int o = 0; o < 8; o++) Q[o] = qb;
    }

    #pragma unroll 1
    for (int c = 0; c < 4; c++) {
        // stage channel c into buf (zero-padded 'SAME')
        if (c < 3) {
            const float* src = fb + c*HW;
            for (int i = tid; i < 38*70; i += 128) {
                int ly = i / 70, lx = i - ly*70;
                int gy = y0 + ly, gx = x0 + lx;
                bool in = (gy >= 0 && gy < H && gx >= 0 && gx < W);
                buf[ROWOFF_F(ly) + lx] = in ? src[gy*W + gx] : 0.f;
            }
        } else {
            for (int i = tid; i < 38*70; i += 128) {
                int ly = i / 70, lx = i - ly*70;
                int gy = y0 + ly, gx = x0 + lx;
                bool in = (gy >= 0 && gy < H && gx >= 0 && gx < W);
                buf[ROWOFF_F(ly) + lx] = in ? (float)lb[gy*W + gx] * invmx : 0.f;
            }
        }
        __syncthreads();

        #pragma unroll
        for (int rr = 0; rr < 8; rr++) {
            const int rbase = ROWOFF_F(2*ty + rr);
            const float* rp = &buf[rbase + tx*8];
            float4 a0 = *(const float4*)(rp);
            float4 a1 = *(const float4*)(rp + 4);
            float4 a2 = *(const float4*)(rp + 8);
            float2 a3 = *(const float2*)(rp + 12);
            unsigned long long dup[14];
            dup[0]  = pack2(a0.x, a0.x);  dup[1]  = pack2(a0.y, a0.y);
            dup[2]  = pack2(a0.z, a0.z);  dup[3]  = pack2(a0.w, a0.w);
            dup[4]  = pack2(a1.x, a1.x);  dup[5]  = pack2(a1.y, a1.y);
            dup[6]  = pack2(a1.z, a1.z);  dup[7]  = pack2(a1.w, a1.w);
            dup[8]  = pack2(a2.x, a2.x);  dup[9]  = pack2(a2.y, a2.y);
            dup[10] = pack2(a2.z, a2.z);  dup[11] = pack2(a2.w, a2.w);
            dup[12] = pack2(a3.x, a3.x);  dup[13] = pack2(a3.y, a3.y);
            #pragma unroll
            for (int kx = 0; kx < 7; kx++) {
                unsigned long long w = *(const unsigned long long*)&wp[c][rr][kx];
                #pragma unroll
                for (int o = 0; o < 8; o++) ffma2(Q[o], dup[o + kx], w);
            }
        }
        __syncthreads();
    }

    // ---- mask + per-thread block partial (both rows in same 8x8 y-block) ----
    float m0[8], m1[8];
    float msum = 0.f;
    #pragma unroll
    for (int o = 0; o < 8; o++) {
        float2 q = unpack2(Q[o]);
        m0[o] = 1.0f / (1.0f + expf(-q.x));
        m1[o] = 1.0f / (1.0f + expf(-q.y));
        msum += m0[o] + m1[o];
    }
    s_part[ty][tx] = msum;
    __syncthreads();

    if (tid < 32) {
        int bh = tid >> 3, bw = tid & 7;
        float s = 0.f;
        #pragma unroll
        for (int i = 0; i < 4; i++) s += s_part[bh*4 + i][bw];
        s_str[bh][bw] = s * (1.0f/64.0f);
    }
    __syncthreads();

    // ---- write mask, embed watermark, write rgb ----
    const int gy0 = by*32 + 2*ty;
    const int gx0 = bx*64 + tx*8;

    if (out_mask) {
        float* mp = out_mask + b*HW + gy0*W + gx0;
        *(float4*)(mp)         = make_float4(m0[0], m0[1], m0[2], m0[3]);
        *(float4*)(mp + 4)     = make_float4(m0[4], m0[5], m0[6], m0[7]);
        *(float4*)(mp + W)     = make_float4(m1[0], m1[1], m1[2], m1[3]);
        *(float4*)(mp + W + 4) = make_float4(m1[4], m1[5], m1[6], m1[7]);
    }

    const float sc0 = g_scale[b*3+0];
    const float sc1 = g_scale[b*3+1];
    const float sc2 = g_scale[b*3+2];

    const int bh_g = gy0 >> 3;
    const int bw_g = gx0 >> 3;
    const float strength = s_str[ty >> 2][tx];
    const int bit = wm[(bh_g*NW + bw_g) % L];
    const float dbase = 0.05f * strength * (2.0f*(float)bit - 1.0f);

    const float* fin = fb + gy0*W + gx0;
    float* outb = out_rgb + b*3*HW + gy0*W + gx0;
    #pragma unroll
    for (int rr = 0; rr < 2; rr++) {
        const float delta = dbase * c_D4[(gy0 + rr) & 7];
        float4 R0 = *(const float4*)(fin + rr*W + 0*HW);
        float4 R1 = *(const float4*)(fin + rr*W + 0*HW + 4);
        float4 G0 = *(const float4*)(fin + rr*W + 1*HW);
        float4 G1 = *(const float4*)(fin + rr*W + 1*HW + 4);
        float4 B0 = *(const float4*)(fin + rr*W + 2*HW);
        float4 B1 = *(const float4*)(fin + rr*W + 2*HW + 4);
        float rv[8] = { R0.x, R0.y, R0.z, R0.w, R1.x, R1.y, R1.z, R1.w };
        float gv[8] = { G0.x, G0.y, G0.z, G0.w, G1.x, G1.y, G1.z, G1.w };
        float bv[8] = { B0.x, B0.y, B0.z, B0.w, B1.x, B1.y, B1.z, B1.w };
        float ro[8], go[8], bo[8];
        #pragma unroll
        for (int o = 0; o < 8; o++) {
            float r  = rv[o], g = gv[o], bl = bv[o];
            float Y =  0.299f*r + 0.587f*g + 0.114f*bl;
            float U = -0.147f*r - 0.289f*g + 0.436f*bl;
            float V =  0.615f*r - 0.515f*g - 0.100f*bl;
            float wy = Y * sc0;
            float wu = U * sc1;
            float wv = V * sc2;
            float ym = wy + delta * c_D3[o];
            ro[o] = ym + 1.140f*wv;
            go[o] = ym - 0.395f*wu - 0.581f*wv;
            bo[o] = ym + 2.032f*wu;
        }
        float* orow = outb + rr*W;
        *(float4*)(orow + 0*HW)     = make_float4(ro[0], ro[1], ro[2], ro[3]);
        *(float4*)(orow + 0*HW + 4) = make_float4(ro[4], ro[5], ro[6], ro[7]);
        *(float4*)(orow + 1*HW)     = make_float4(go[0], go[1], go[2], go[3]);
        *(float4*)(orow + 1*HW + 4) = make_float4(go[4], go[5], go[6], go[7]);
        *(float4*)(orow + 2*HW)     = make_float4(bo[0], bo[1], bo[2], bo[3]);
        *(float4*)(orow + 2*HW + 4) = make_float4(bo[4], bo[5], bo[6], bo[7]);
    }
}

extern "C" void kernel_launch(void* const* d_in, const int* in_sizes, int n_in,
                              void* d_out, int out_size) {
    const float* frame = (const float*)d_in[0];
    const int*   wm    = (const int*)  d_in[1];
    const float* sa_w  = (const float*)d_in[2];
    const float* sa_b  = (const float*)d_in[3];
    const float* ca_w1 = (const float*)d_in[4];
    const float* ca_w2 = (const float*)d_in[5];
    int L = in_sizes[1];

    float* out = (float*)d_out;
    const long rgbN = (long)BB*3*HW;
    float* out_mask = ((long)out_size >= rgbN + (long)BB*HW) ? out + rgbN : nullptr;

    dim3 grd1(8, 16, BB);
    k1_lbp<<<grd1, 256>>>(frame);

    k2_scale<<<1, 16>>>(ca_w1, ca_w2);

    dim3 grd3(8, 16, BB);
    k3_fused<<<grd3, 128>>>(frame, sa_w, sa_b, wm, L, out, out_mask);
}

// round 15
// speedup vs baseline: 1.2573x; 1.1487x over previous
#include <cuda_runtime.h>
#include <math.h>

#define BB 16
#define H 512
#define W 512
#define NH 64
#define NW 64
#define HW (H*W)
#define NCTA1 128   // k1 CTAs per batch (8 x 16)

// Scratch (no allocations allowed)
__device__ unsigned char g_lbp8[BB*HW];     // LBP code 0..9 as u8
__device__ float4 g_partials4[BB*NCTA1];    // per-CTA {sum_r, sum_g, sum_b, max_code}
__device__ float g_scale[BB*3];
__device__ float g_invmx[BB];

// D[4,:] and D[3,:] of the 8x8 DCT-II matrix (with row scaling)
__constant__ float c_D4[8] = {
    0.35355339059327373f, -0.35355339059327373f, -0.35355339059327373f,  0.35355339059327373f,
    0.35355339059327373f, -0.35355339059327373f, -0.35355339059327373f,  0.35355339059327373f };
__constant__ float c_D3[8] = {
    0.4157348061512726f,  -0.0975451610080642f,  -0.4903926402016152f,  -0.2777851165098011f,
    0.2777851165098011f,   0.4903926402016152f,   0.0975451610080642f,  -0.4157348061512726f };

__device__ __forceinline__ unsigned long long pack2(float lo, float hi) {
    unsigned long long r;
    asm("mov.b64 %0, {%1, %2};" : "=l"(r) : "f"(lo), "f"(hi));
    return r;
}
__device__ __forceinline__ float2 unpack2(unsigned long long v) {
    float2 f;
    asm("mov.b64 {%0, %1}, %2;" : "=f"(f.x), "=f"(f.y) : "l"(v));
    return f;
}
__device__ __forceinline__ void ffma2(unsigned long long& d, unsigned long long a, unsigned long long b) {
    asm("fma.rn.f32x2 %0, %1, %2, %0;" : "+l"(d) : "l"(a), "l"(b));
}

// ---------------- K1: LBP code (u8) + per-batch max + rgb partial sums --------
// 64x32 output tile per CTA. 256 threads as (tx=tid&31, tyy=tid>>5).
// Halo tile gs[34][0..65]: gs[r][lx] = gray at (by*32+r-1, bx*64+lx-1), clamped.
__global__ __launch_bounds__(256) void k1_lbp(const float* __restrict__ frame) {
    const int b  = blockIdx.z;
    const int bx = blockIdx.x;   // 0..7
    const int by = blockIdx.y;   // 0..15
    const int tid = threadIdx.x;
    const int tx  = tid & 31;
    const int tyy = tid >> 5;    // 0..7

    __shared__ float gs[34][68];
    __shared__ float4 wred[8];

    const float* fb = frame + b*3*HW;

    float sr = 0.f, sg = 0.f, sb = 0.f;
    for (int r = tyy; r < 34; r += 8) {
        int gy = min(max(by*32 + r - 1, 0), H-1);
        const float* rowp = fb + gy*W;
        const bool rin = (r >= 1 && r <= 32);

        // col group 0: lx = tx (0..31)
        {
            int lx = tx;
            int gx = min(max(bx*64 + lx - 1, 0), W-1);
            float rv = rowp[gx], gv = rowp[HW + gx], bv = rowp[2*HW + gx];
            gs[r][lx] = 0.299f*rv + 0.587f*gv + 0.114f*bv;
            if (rin && lx >= 1) { sr += rv; sg += gv; sb += bv; }
        }
        // col group 1: lx = tx+32 (32..63), always interior in x
        {
            int lx = tx + 32;
            int gx = min(max(bx*64 + lx - 1, 0), W-1);
            float rv = rowp[gx], gv = rowp[HW + gx], bv = rowp[2*HW + gx];
            gs[r][lx] = 0.299f*rv + 0.587f*gv + 0.114f*bv;
            if (rin) { sr += rv; sg += gv; sb += bv; }
        }
        // col group 2: lx = tx+64 (64,65) for tx<2
        if (tx < 2) {
            int lx = tx + 64;
            int gx = min(max(bx*64 + lx - 1, 0), W-1);
            float rv = rowp[gx], gv = rowp[HW + gx], bv = rowp[2*HW + gx];
            gs[r][lx] = 0.299f*rv + 0.587f*gv + 0.114f*bv;
            if (rin && lx <= 64) { sr += rv; sg += gv; sb += bv; }
        }
    }
    __syncthreads();

    float lmax = 0.f;
    unsigned char* lbp = g_lbp8 + b*HW;
    #pragma unroll
    for (int k = 0; k < 8; k++) {
        int idx = tid + k*256;
        int y = idx >> 6, x = idx & 63;
        int ly = y + 1, lx = x + 1;
        float c = gs[ly][lx];
        // offs order: (-1,0),(-1,1),(0,1),(1,1),(1,0),(1,-1),(0,-1),(-1,-1)
        unsigned bits = 0;
        bits |= (gs[ly-1][lx  ] >= c) ?   1u : 0u;
        bits |= (gs[ly-1][lx+1] >= c) ?   2u : 0u;
        bits |= (gs[ly  ][lx+1] >= c) ?   4u : 0u;
        bits |= (gs[ly+1][lx+1] >= c) ?   8u : 0u;
        bits |= (gs[ly+1][lx  ] >= c) ?  16u : 0u;
        bits |= (gs[ly+1][lx-1] >= c) ?  32u : 0u;
        bits |= (gs[ly  ][lx-1] >= c) ?  64u : 0u;
        bits |= (gs[ly-1][lx-1] >= c) ? 128u : 0u;
        int s = __popc(bits);
        unsigned rot = ((bits << 1) | (bits >> 7)) & 0xffu;
        int trans = __popc(bits ^ rot);
        int code = (trans <= 2) ? s : 9;
        lbp[(by*32 + y)*W + bx*64 + x] = (unsigned char)code;
        lmax = fmaxf(lmax, (float)code);
    }

    #pragma unroll
    for (int off = 16; off > 0; off >>= 1) {
        sr   += __shfl_down_sync(0xffffffffu, sr, off);
        sg   += __shfl_down_sync(0xffffffffu, sg, off);
        sb   += __shfl_down_sync(0xffffffffu, sb, off);
        lmax  = fmaxf(lmax, __shfl_down_sync(0xffffffffu, lmax, off));
    }
    if ((tid & 31) == 0) wred[tid >> 5] = make_float4(sr, sg, sb, lmax);
    __syncthreads();
    if (tid == 0) {
        float4 a = wred[0];
        #pragma unroll
        for (int w = 1; w < 8; w++) {
            float4 c = wred[w];
            a.x += c.x; a.y += c.y; a.z += c.z; a.w = fmaxf(a.w, c.w);
        }
        g_partials4[b*NCTA1 + by*8 + bx] = a;
    }
}

// ---------------- K2: channel-attention scale + 1/max ------------------------
__global__ void k2_scale(const float* __restrict__ caw1, const float* __restrict__ caw2) {
    int b = threadIdx.x;
    if (b >= BB) return;
    float sr = 0.f, sg = 0.f, sb = 0.f, mx = 0.f;
    for (int i = 0; i < NCTA1; i++) {
        float4 a = g_partials4[b*NCTA1 + i];
        sr += a.x; sg += a.y; sb += a.z; mx = fmaxf(mx, a.w);
    }
    const float inv = 1.0f / (float)(HW);
    float mr = sr*inv, mg = sg*inv, mb = sb*inv;
    float p[3];
    p[0] =  0.299f*mr + 0.587f*mg + 0.114f*mb;
    p[1] = -0.147f*mr - 0.289f*mg + 0.436f*mb;
    p[2] =  0.615f*mr - 0.515f*mg - 0.100f*mb;
    float h[3];
    #pragma unroll
    for (int i = 0; i < 3; i++) {
        float a = p[0]*caw1[i*3+0] + p[1]*caw1[i*3+1] + p[2]*caw1[i*3+2];
        h[i] = fmaxf(a, 0.f);
    }
    #pragma unroll
    for (int i = 0; i < 3; i++) {
        float a = h[0]*caw2[i*3+0] + h[1]*caw2[i*3+1] + h[2]*caw2[i*3+2];
        g_scale[b*3+i] = 1.0f / (1.0f + expf(-a));
    }
    g_invmx[b] = 1.0f / mx;
}

// ---------------- K3 fused (R4 champion): staged conv (f32x2 dup) ------------
// Output tile per CTA: 64 (x) x 32 (y). 128 threads: tx=tid&7, ty=tid>>3.
// Each thread: 8 x-outputs x 2 y-rows, packed into 8 f32x2 accumulators.
__global__ __launch_bounds__(128, 7) void k3_fused(const float* __restrict__ frame,
                                                   const float* __restrict__ sa_w,
                                                   const float* __restrict__ sa_b,
                                                   const int* __restrict__ wm, int L,
                                                   float* __restrict__ out_rgb,
                                                   float* __restrict__ out_mask) {
    const int b  = blockIdx.z;
    const int bx = blockIdx.x;   // 0..7
    const int by = blockIdx.y;   // 0..15
    const int tid = threadIdx.x;
    const int tx = tid & 7;      // 0..7
    const int ty = tid >> 3;     // 0..15

    __shared__ __align__(16) float buf[38][72];     // one channel stage
    __shared__ __align__(8)  float2 wp[4][8][7];    // (w[rr], w[rr-1]) pairs, zero-padded
    __shared__ float s_bias;
    __shared__ float s_part[16][8];
    __shared__ float s_str[4][8];

    // Pre-pack weight pairs: lo half drives acc0 (y-row 2ty), hi half acc1 (2ty+1)
    for (int i = tid; i < 224; i += 128) {
        int c = i / 56, rem = i % 56, rr = rem / 7, kx = rem % 7;
        float lo = (rr < 7) ? sa_w[c*49 + rr*7 + kx]     : 0.f;
        float hi = (rr >= 1) ? sa_w[c*49 + (rr-1)*7 + kx] : 0.f;
        wp[c][rr][kx] = make_float2(lo, hi);
    }
    if (tid == 0) s_bias = sa_b[0];
    __syncthreads();

    const float invmx = g_invmx[b];
    const float* fb = frame + b*3*HW;
    const unsigned char* lb = g_lbp8 + b*HW;
    const int y0 = by*32 - 3, x0 = bx*64 - 3;

    unsigned long long Q[8];
    {
        const unsigned long long qb = pack2(s_bias, s_bias);
        #pragma unroll
        for (int o = 0; o < 8; o++) Q[o] = qb;
    }

    #pragma unroll 1
    for (int c = 0; c < 4; c++) {
        // stage channel c into buf (zero-padded 'SAME')
        if (c < 3) {
            const float* src = fb + c*HW;
            for (int i = tid; i < 38*70; i += 128) {
                int ly = i / 70, lx = i % 70;
                int gy = y0 + ly, gx = x0 + lx;
                bool in = (gy >= 0 && gy < H && gx >= 0 && gx < W);
                buf[ly][lx] = in ? src[gy*W + gx] : 0.f;
            }
        } else {
            for (int i = tid; i < 38*70; i += 128) {
                int ly = i / 70, lx = i % 70;
                int gy = y0 + ly, gx = x0 + lx;
                bool in = (gy >= 0 && gy < H && gx >= 0 && gx < W);
                buf[ly][lx] = in ? (float)lb[gy*W + gx] * invmx : 0.f;
            }
        }
        __syncthreads();

        #pragma unroll
        for (int rr = 0; rr < 8; rr++) {
            const float* rp = &buf[2*ty + rr][tx*8];
            float4 a0 = *(const float4*)(rp);
            float4 a1 = *(const float4*)(rp + 4);
            float4 a2 = *(const float4*)(rp + 8);
            float2 a3 = *(const float2*)(rp + 12);
            unsigned long long dup[14];
            dup[0]  = pack2(a0.x, a0.x);  dup[1]  = pack2(a0.y, a0.y);
            dup[2]  = pack2(a0.z, a0.z);  dup[3]  = pack2(a0.w, a0.w);
            dup[4]  = pack2(a1.x, a1.x);  dup[5]  = pack2(a1.y, a1.y);
            dup[6]  = pack2(a1.z, a1.z);  dup[7]  = pack2(a1.w, a1.w);
            dup[8]  = pack2(a2.x, a2.x);  dup[9]  = pack2(a2.y, a2.y);
            dup[10] = pack2(a2.z, a2.z);  dup[11] = pack2(a2.w, a2.w);
            dup[12] = pack2(a3.x, a3.x);  dup[13] = pack2(a3.y, a3.y);
            #pragma unroll
            for (int kx = 0; kx < 7; kx++) {
                unsigned long long w = *(const unsigned long long*)&wp[c][rr][kx];
                #pragma unroll
                for (int o = 0; o < 8; o++) ffma2(Q[o], dup[o + kx], w);
            }
        }
        __syncthreads();
    }

    // ---- mask + per-thread block partial ----
    float m0[8], m1[8];
    float msum = 0.f;
    #pragma unroll
    for (int o = 0; o < 8; o++) {
        float2 q = unpack2(Q[o]);
        m0[o] = 1.0f / (1.0f + expf(-q.x));
        m1[o] = 1.0f / (1.0f + expf(-q.y));
        msum += m0[o] + m1[o];
    }
    s_part[ty][tx] = msum;
    __syncthreads();

    if (tid < 32) {
        int bh = tid >> 3, bw = tid & 7;
        float s = 0.f;
        #pragma unroll
        for (int i = 0; i < 4; i++) s += s_part[bh*4 + i][bw];
        s_str[bh][bw] = s * (1.0f/64.0f);
    }
    __syncthreads();

    // ---- write mask, embed watermark, write rgb ----
    const int gy0 = by*32 + 2*ty;
    const int gx0 = bx*64 + tx*8;

    if (out_mask) {
        float* mp = out_mask + b*HW + gy0*W + gx0;
        *(float4*)(mp)         = make_float4(m0[0], m0[1], m0[2], m0[3]);
        *(float4*)(mp + 4)     = make_float4(m0[4], m0[5], m0[6], m0[7]);
        *(float4*)(mp + W)     = make_float4(m1[0], m1[1], m1[2], m1[3]);
        *(float4*)(mp + W + 4) = make_float4(m1[4], m1[5], m1[6], m1[7]);
    }

    const float sc0 = g_scale[b*3+0];
    const float sc1 = g_scale[b*3+1];
    const float sc2 = g_scale[b*3+2];

    const int bh_g = gy0 >> 3;
    const int bw_g = gx0 >> 3;
    const float strength = s_str[ty >> 2][tx];
    const int bit = wm[(bh_g*NW + bw_g) % L];
    const float dbase = 0.05f * strength * (2.0f*(float)bit - 1.0f);

    const float* fin = fb + gy0*W + gx0;
    float* outb = out_rgb + b*3*HW + gy0*W + gx0;
    #pragma unroll
    for (int rr = 0; rr < 2; rr++) {
        const float delta = dbase * c_D4[(gy0 + rr) & 7];
        float4 R0 = *(const float4*)(fin + rr*W + 0*HW);
        float4 R1 = *(const float4*)(fin + rr*W + 0*HW + 4);
        float4 G0 = *(const float4*)(fin + rr*W + 1*HW);
        float4 G1 = *(const float4*)(fin + rr*W + 1*HW + 4);
        float4 B0 = *(const float4*)(fin + rr*W + 2*HW);
        float4 B1 = *(const float4*)(fin + rr*W + 2*HW + 4);
        float rv[8] = { R0.x, R0.y, R0.z, R0.w, R1.x, R1.y, R1.z, R1.w };
        float gv[8] = { G0.x, G0.y, G0.z, G0.w, G1.x, G1.y, G1.z, G1.w };
        float bv[8] = { B0.x, B0.y, B0.z, B0.w, B1.x, B1.y, B1.z, B1.w };
        float ro[8], go[8], bo[8];
        #pragma unroll
        for (int o = 0; o < 8; o++) {
            float r  = rv[o], g = gv[o], bl = bv[o];
            float Y =  0.299f*r + 0.587f*g + 0.114f*bl;
            float U = -0.147f*r - 0.289f*g + 0.436f*bl;
            float V =  0.615f*r - 0.515f*g - 0.100f*bl;
            float wy = Y * sc0;
            float wu = U * sc1;
            float wv = V * sc2;
            float ym = wy + delta * c_D3[o];
            ro[o] = ym + 1.140f*wv;
            go[o] = ym - 0.395f*wu - 0.581f*wv;
            bo[o] = ym + 2.032f*wu;
        }
        float* orow = outb + rr*W;
        *(float4*)(orow + 0*HW)     = make_float4(ro[0], ro[1], ro[2], ro[3]);
        *(float4*)(orow + 0*HW + 4) = make_float4(ro[4], ro[5], ro[6], ro[7]);
        *(float4*)(orow + 1*HW)     = make_float4(go[0], go[1], go[2], go[3]);
        *(float4*)(orow + 1*HW + 4) = make_float4(go[4], go[5], go[6], go[7]);
        *(float4*)(orow + 2*HW)     = make_float4(bo[0], bo[1], bo[2], bo[3]);
        *(float4*)(orow + 2*HW + 4) = make_float4(bo[4], bo[5], bo[6], bo[7]);
    }
}

extern "C" void kernel_launch(void* const* d_in, const int* in_sizes, int n_in,
                              void* d_out, int out_size) {
    const float* frame = (const float*)d_in[0];
    const int*   wm    = (const int*)  d_in[1];
    const float* sa_w  = (const float*)d_in[2];
    const float* sa_b  = (const float*)d_in[3];
    const float* ca_w1 = (const float*)d_in[4];
    const float* ca_w2 = (const float*)d_in[5];
    int L = in_sizes[1];

    float* out = (float*)d_out;
    const long rgbN = (long)BB*3*HW;
    float* out_mask = ((long)out_size >= rgbN + (long)BB*HW) ? out + rgbN : nullptr;

    dim3 grd1(8, 16, BB);
    k1_lbp<<<grd1, 256>>>(frame);

    k2_scale<<<1, 16>>>(ca_w1, ca_w2);

    dim3 grd3(8, 16, BB);
    k3_fused<<<grd3, 128>>>(frame, sa_w, sa_b, wm, L, out, out_mask);
}